// round 4
// baseline (speedup 1.0000x reference)
#include <cuda_runtime.h>
#include <cuda_bf16.h>

// Problem constants
#define BATCH   64
#define TSTEPS  1024
#define DIM     512          // D_in == D_out == 512
#define NCTA    128          // persistent grid size (<= 148 SMs -> co-resident)

// ---------------- scratch (device globals; no allocations allowed) ----------
__device__ float    g_xw[BATCH * TSTEPS * DIM];   // 134 MB precomputed x@W + b
__device__ float    g_h[2][BATCH * DIM];          // ping-pong hidden state
__device__ unsigned g_bar[TSTEPS];                // per-step grid barrier counters

// ============================================================================
// Kernel 1: XW = reshape(x,[B*T,512]) @ W[512,512] + bias   (fp32 SIMT GEMM)
// BM=128, BN=64, BK=16, 256 threads, 8x4 outputs per thread
// ============================================================================
#define BM 128
#define BN 64
#define BK 16

__global__ void __launch_bounds__(256) gemm_xw_kernel(
    const float* __restrict__ X,      // [65536, 512]
    const float* __restrict__ W,      // [512, 512]
    const float* __restrict__ bias,   // [512]
    float* __restrict__ XW)           // [65536, 512]
{
    __shared__ float As[BK * BM];     // transposed: As[k][m]
    __shared__ float Bs[BK * BN];     // Bs[k][n]

    const int tid = threadIdx.x;
    const int bm  = blockIdx.x * BM;
    const int bn  = blockIdx.y * BN;

    // A-load mapping: 128 rows x 16 k -> thread loads 2 float4 along k
    const int a_row = tid >> 1;
    const int a_k   = (tid & 1) * 8;
    // B-load mapping: 16 k x 64 n -> thread loads 1 float4 along n
    const int b_k   = tid >> 4;
    const int b_n   = (tid & 15) * 4;
    // compute mapping: 16x16 thread grid, 8 rows x 4 cols each
    const int ty = tid >> 4;
    const int tx = tid & 15;

    float acc[8][4];
#pragma unroll
    for (int i = 0; i < 8; i++)
#pragma unroll
        for (int j = 0; j < 4; j++) acc[i][j] = 0.f;

    for (int k0 = 0; k0 < DIM; k0 += BK) {
        // load A tile (transpose into As[k][m])
        float4 a0 = *(const float4*)&X[(size_t)(bm + a_row) * DIM + k0 + a_k];
        float4 a1 = *(const float4*)&X[(size_t)(bm + a_row) * DIM + k0 + a_k + 4];
        As[(a_k + 0) * BM + a_row] = a0.x;
        As[(a_k + 1) * BM + a_row] = a0.y;
        As[(a_k + 2) * BM + a_row] = a0.z;
        As[(a_k + 3) * BM + a_row] = a0.w;
        As[(a_k + 4) * BM + a_row] = a1.x;
        As[(a_k + 5) * BM + a_row] = a1.y;
        As[(a_k + 6) * BM + a_row] = a1.z;
        As[(a_k + 7) * BM + a_row] = a1.w;
        // load B tile
        *(float4*)&Bs[b_k * BN + b_n] =
            *(const float4*)&W[(size_t)(k0 + b_k) * DIM + bn + b_n];
        __syncthreads();

#pragma unroll
        for (int kk = 0; kk < BK; kk++) {
            float ar[8], br[4];
            *(float4*)&ar[0] = *(const float4*)&As[kk * BM + ty * 8];
            *(float4*)&ar[4] = *(const float4*)&As[kk * BM + ty * 8 + 4];
            *(float4*)&br[0] = *(const float4*)&Bs[kk * BN + tx * 4];
#pragma unroll
            for (int i = 0; i < 8; i++)
#pragma unroll
                for (int j = 0; j < 4; j++)
                    acc[i][j] = fmaf(ar[i], br[j], acc[i][j]);
        }
        __syncthreads();
    }

    // epilogue: add bias, store
    float4 bv = *(const float4*)&bias[bn + tx * 4];
#pragma unroll
    for (int i = 0; i < 8; i++) {
        float4 o;
        o.x = acc[i][0] + bv.x;
        o.y = acc[i][1] + bv.y;
        o.z = acc[i][2] + bv.z;
        o.w = acc[i][3] + bv.w;
        *(float4*)&XW[(size_t)(bm + ty * 8 + i) * DIM + bn + tx * 4] = o;
    }
}

// ============================================================================
// Kernel 2: persistent recurrent loop.
// 128 CTAs x 256 threads. CTA (bg, jg): b-rows [bg*8, bg*8+8), cols [jg*32,+32).
// Thread layout: warp = kq (k-quarter-of-64), lane = j_local.
// W_r slice lives in registers (64 floats/thread) for the whole kernel.
// Per step: stage h-tile (16KB, __ldcg, L2-coherent) -> 512 FFMA/thread ->
// cross-warp reduce in smem -> tanh -> store h ping-pong -> grid barrier.
// ============================================================================
__global__ void __launch_bounds__(256, 1) rnn_persistent_kernel(
    const float* __restrict__ Wr,     // [512, 512] row-major: Wr[k*512 + j]
    const float* __restrict__ xw,     // [B, T, 512]
    float* __restrict__ out)          // [B, 512]
{
    __shared__ float hs[8 * DIM];          // 16 KB staged h tile
    __shared__ float part[8 * 8 * 32];     // 8 KB partial sums [kq][bl][j]

    const int tid  = threadIdx.x;
    const int kq   = tid >> 5;             // warp id 0..7 -> k range [kq*64, +64)
    const int lane = tid & 31;             // j_local
    const int c    = blockIdx.x;
    const int b0   = (c >> 4) * 8;         // 8 batch-groups
    const int j0   = (c & 15) * 32;        // 16 column-groups

    // Load persistent W_r slice into registers: w_reg[i] = Wr[kq*64+i][j0+lane]
    float w_reg[64];
#pragma unroll
    for (int i = 0; i < 64; i++)
        w_reg[i] = Wr[(size_t)(kq * 64 + i) * DIM + j0 + lane];

    // reduction-phase mapping (reuse all 256 threads: 8 bl x 32 j)
    const int rbl = tid >> 5;
    const int rj  = lane;

    for (int t = 0; t < TSTEPS; t++) {
        const float* hcur = g_h[t & 1];

        // ---- stage h tile: 8 rows x 512 = 1024 float4, 4 per thread ----
        {
            const float4* src = (const float4*)(hcur + b0 * DIM);
#pragma unroll
            for (int q = 0; q < 4; q++) {
                int idx = tid + q * 256;
                float4 v = __ldcg(src + idx);        // bypass L1 (cross-CTA data)
                *(float4*)&hs[idx * 4] = v;
            }
        }
        __syncthreads();

        // ---- partial matmul: acc[bl] = sum_{k in kq-range} hs[bl][k]*w_reg ----
        float acc[8];
#pragma unroll
        for (int bl = 0; bl < 8; bl++) acc[bl] = 0.f;
#pragma unroll
        for (int bl = 0; bl < 8; bl++) {
            const float* hrow = &hs[bl * DIM + kq * 64];
#pragma unroll
            for (int i = 0; i < 64; i += 4) {
                float4 h4 = *(const float4*)&hrow[i];   // broadcast across lanes
                acc[bl] = fmaf(h4.x, w_reg[i + 0], acc[bl]);
                acc[bl] = fmaf(h4.y, w_reg[i + 1], acc[bl]);
                acc[bl] = fmaf(h4.z, w_reg[i + 2], acc[bl]);
                acc[bl] = fmaf(h4.w, w_reg[i + 3], acc[bl]);
            }
        }
#pragma unroll
        for (int bl = 0; bl < 8; bl++)
            part[kq * 256 + bl * 32 + lane] = acc[bl];
        __syncthreads();

        // ---- reduce over kq, add xw, tanh, write ----
        {
            float s = 0.f;
#pragma unroll
            for (int q = 0; q < 8; q++)
                s += part[q * 256 + rbl * 32 + rj];
            s += xw[((size_t)(b0 + rbl) * TSTEPS + t) * DIM + j0 + rj];
            float hv = tanhf(s);
            if (t == TSTEPS - 1) {
                out[(b0 + rbl) * DIM + j0 + rj] = hv;
            } else {
                g_h[(t + 1) & 1][(b0 + rbl) * DIM + j0 + rj] = hv;
            }
        }

        if (t == TSTEPS - 1) break;

        // ---- grid barrier (monotonic counters, reset by memset each launch) --
        __threadfence();          // make h stores visible at L2 before arrival
        __syncthreads();          // all threads' stores done before signaling
        if (tid == 0) {
            atomicAdd(&g_bar[t], 1u);
            volatile unsigned* p = &g_bar[t];
            while (*p < NCTA) { }
            __threadfence();      // acquire: order subsequent h reads
        }
        __syncthreads();
    }
}

// ============================================================================
extern "C" void kernel_launch(void* const* d_in, const int* in_sizes, int n_in,
                              void* d_out, int out_size)
{
    const float* x    = (const float*)d_in[0];   // [64,1024,512]
    const float* W    = (const float*)d_in[1];   // [512,512]
    const float* Wr   = (const float*)d_in[2];   // [512,512]
    const float* bias = (const float*)d_in[3];   // [512]
    float* out = (float*)d_out;                  // [64,512]

    float* xw_p; cudaGetSymbolAddress((void**)&xw_p, g_xw);
    void*  bar_p; cudaGetSymbolAddress(&bar_p, g_bar);
    void*  h_p;   cudaGetSymbolAddress(&h_p, g_h);

    // per-launch resets (graph-capturable, replay-safe)
    cudaMemsetAsync(bar_p, 0, sizeof(unsigned) * TSTEPS);
    cudaMemsetAsync(h_p, 0, sizeof(float) * BATCH * DIM);  // zero h_0 (buffer 0)

    dim3 ggrid((BATCH * TSTEPS) / BM, DIM / BN);           // 512 x 8
    gemm_xw_kernel<<<ggrid, 256>>>(x, W, bias, xw_p);

    rnn_persistent_kernel<<<NCTA, 256>>>(Wr, xw_p, out);
}

// round 5
// speedup vs baseline: 1.0230x; 1.0230x over previous
#include <cuda_runtime.h>

#define BATCH   64
#define TSTEPS  1024
#define DIM     512
#define NCTA    128      // 8 b-groups x 16 j-groups; <=148 SMs -> co-resident

// ---------------- scratch (device globals; no allocations) ------------------
__device__ float    g_h[2][BATCH * DIM];   // ping-pong hidden state
__device__ unsigned g_bar[TSTEPS];         // per-step monotonic barrier counters

// ---------------- f32x2 packed-FMA helpers (sm_100+ PTX) --------------------
static __device__ __forceinline__ unsigned long long packf2(float lo, float hi) {
    unsigned long long r;
    asm("mov.b64 %0, {%1, %2};" : "=l"(r) : "f"(lo), "f"(hi));
    return r;
}
static __device__ __forceinline__ void unpackf2(unsigned long long v, float& lo, float& hi) {
    asm("mov.b64 {%0, %1}, %2;" : "=f"(lo), "=f"(hi) : "l"(v));
}
static __device__ __forceinline__ unsigned long long fma2(
    unsigned long long a, unsigned long long b, unsigned long long c) {
    unsigned long long d;
    asm("fma.rn.f32x2 %0, %1, %2, %3;" : "=l"(d) : "l"(a), "l"(b), "l"(c));
    return d;
}

// ---------------------------------------------------------------------------
// One matmul unit: partials for 8 rows x 32 cols over this warp's 64-k slice.
//   sm:   staged tile [8][512] in smem
//   w2:   32 packed weight pairs (k, k+1) for column j0+lane (in registers)
// Writes part[kq*256 + bl*32 + lane] = dot(sm[bl][kq*64 .. +64], w_col).
// m-outer loop -> 8 independent acc chains, latency fully hidden.
// ---------------------------------------------------------------------------
static __device__ __forceinline__ void mm_partials(
    const float* __restrict__ sm, const unsigned long long* w2,
    int kq, int lane, float* __restrict__ part)
{
    unsigned long long acc[8];
#pragma unroll
    for (int bl = 0; bl < 8; bl++) acc[bl] = 0ULL;

#pragma unroll
    for (int m = 0; m < 16; m++) {
#pragma unroll
        for (int bl = 0; bl < 8; bl++) {
            // LDS.128 broadcast: 4 floats = 2 packed pairs (k..k+3)
            ulonglong2 h2 = *(const ulonglong2*)(sm + bl * DIM + kq * 64 + m * 4);
            acc[bl] = fma2(h2.x, w2[2 * m + 0], acc[bl]);
            acc[bl] = fma2(h2.y, w2[2 * m + 1], acc[bl]);
        }
    }
#pragma unroll
    for (int bl = 0; bl < 8; bl++) {
        float lo, hi;
        unpackf2(acc[bl], lo, hi);
        part[kq * 256 + bl * 32 + lane] = lo + hi;
    }
}

// ---------------------------------------------------------------------------
// Fused persistent kernel: per step t
//   h_{t+1} = tanh( xw_reg[t] + h_t @ Wr )      (xw_reg holds x_t @ W + b)
// and, between barrier-arrive and barrier-wait, computes xw_reg[t+1].
// CTA c: rows [b0, b0+8), cols [j0, j0+32). warp = k-slice, lane = column.
// ---------------------------------------------------------------------------
__global__ void __launch_bounds__(256, 1) rnn_fused_kernel(
    const float* __restrict__ W,      // [512,512] row-major
    const float* __restrict__ Wr,     // [512,512] row-major
    const float* __restrict__ x,      // [64,1024,512]
    const float* __restrict__ bias,   // [512]
    float* __restrict__ out)          // [64,512]
{
    __shared__ float hs[8 * DIM];            // 16 KB staged h tile
    __shared__ float xs[8 * DIM];            // 16 KB staged x tile (t+1)
    __shared__ float part[8 * 8 * 32];       // 8 KB partials [kq][bl][j]

    const int tid  = threadIdx.x;
    const int kq   = tid >> 5;               // warp id: k range [kq*64, +64)
    const int lane = tid & 31;               // column within j-group
    const int c    = blockIdx.x;
    const int b0   = (c >> 4) * 8;
    const int j0   = (c & 15) * 32;

    // persistent packed weights: pair (k, k+1) for column j0+lane
    unsigned long long wr2[32], wx2[32];
#pragma unroll
    for (int p = 0; p < 32; p++) {
        int k = kq * 64 + 2 * p;
        wr2[p] = packf2(Wr[(size_t)k * DIM + j0 + lane],
                        Wr[(size_t)(k + 1) * DIM + j0 + lane]);
        wx2[p] = packf2(W[(size_t)k * DIM + j0 + lane],
                        W[(size_t)(k + 1) * DIM + j0 + lane]);
    }
    const float bv  = bias[j0 + lane];
    const int   rbl = tid >> 5;              // reduce-phase row
    const int   rj  = lane;                  // reduce-phase col

    // ---- prologue: xw for t = 0 -> register ----
#pragma unroll
    for (int q = 0; q < 4; q++) {
        int idx = tid + q * 256, row = idx >> 7, cc = idx & 127;
        *(float4*)&xs[row * DIM + cc * 4] =
            __ldg((const float4*)(x + ((size_t)(b0 + row) * TSTEPS + 0) * DIM + cc * 4));
    }
    __syncthreads();
    mm_partials(xs, wx2, kq, lane, part);
    __syncthreads();
    float xw_cur = bv;
#pragma unroll
    for (int q = 0; q < 8; q++) xw_cur += part[q * 256 + rbl * 32 + rj];
    __syncthreads();                         // guard part reuse

    for (int t = 0; t < TSTEPS; t++) {
        // ---- stage h tile (L2-coherent) ----
        const float4* hsrc = (const float4*)(g_h[t & 1] + b0 * DIM);
#pragma unroll
        for (int q = 0; q < 4; q++) {
            int idx = tid + q * 256;
            *(float4*)&hs[idx * 4] = __ldcg(hsrc + idx);
        }
        // ---- prefetch x tile for t+1 into registers (latency hidden) ----
        float4 xt[4];
        const int tn = (t + 1 < TSTEPS) ? (t + 1) : (TSTEPS - 1);
#pragma unroll
        for (int q = 0; q < 4; q++) {
            int idx = tid + q * 256, row = idx >> 7, cc = idx & 127;
            xt[q] = __ldg((const float4*)(
                x + ((size_t)(b0 + row) * TSTEPS + tn) * DIM + cc * 4));
        }
        __syncthreads();                     // hs visible

        // ---- recurrence: h_t @ Wr partials ----
        mm_partials(hs, wr2, kq, lane, part);
        __syncthreads();

        // ---- reduce + tanh + store h ----
        float s = xw_cur;
#pragma unroll
        for (int q = 0; q < 8; q++) s += part[q * 256 + rbl * 32 + rj];
        float hv = tanhf(s);
        if (t == TSTEPS - 1) {
            out[(b0 + rbl) * DIM + j0 + rj] = hv;
            return;
        }
        __stcg(&g_h[(t + 1) & 1][(b0 + rbl) * DIM + j0 + rj], hv);
        __threadfence();                     // h visible at L2 before arrival
        __syncthreads();                     // all stores done + part reads done

        if (tid == 0) atomicAdd(&g_bar[t], 1u);   // arrive (don't wait yet)

        // ---- gemm for t+1 fills the barrier-wait window ----
#pragma unroll
        for (int q = 0; q < 4; q++) {
            int idx = tid + q * 256, row = idx >> 7, cc = idx & 127;
            *(float4*)&xs[row * DIM + cc * 4] = xt[q];
        }
        __syncthreads();                     // xs visible
        mm_partials(xs, wx2, kq, lane, part);
        __syncthreads();
        float s2 = bv;
#pragma unroll
        for (int q = 0; q < 8; q++) s2 += part[q * 256 + rbl * 32 + rj];
        xw_cur = s2;

        // ---- barrier wait ----
        if (tid == 0) {
            volatile unsigned* p = &g_bar[t];
            while (*p < NCTA) { }
            __threadfence();                 // acquire
        }
        __syncthreads();
    }
}

// ============================================================================
extern "C" void kernel_launch(void* const* d_in, const int* in_sizes, int n_in,
                              void* d_out, int out_size)
{
    const float* x    = (const float*)d_in[0];   // [64,1024,512]
    const float* W    = (const float*)d_in[1];   // [512,512]
    const float* Wr   = (const float*)d_in[2];   // [512,512]
    const float* bias = (const float*)d_in[3];   // [512]
    float* out = (float*)d_out;                  // [64,512]

    void* bar_p; cudaGetSymbolAddress(&bar_p, g_bar);
    void* h_p;   cudaGetSymbolAddress(&h_p, g_h);

    // per-launch resets (graph-capturable, replay-safe)
    cudaMemsetAsync(bar_p, 0, sizeof(unsigned) * TSTEPS);
    cudaMemsetAsync(h_p, 0, sizeof(float) * BATCH * DIM);   // h_0 = 0 (buffer 0)

    rnn_fused_kernel<<<NCTA, 256>>>(W, Wr, x, bias, out);
}

// round 7
// speedup vs baseline: 1.4115x; 1.3798x over previous
#include <cuda_runtime.h>

#define BATCH   64
#define TSTEPS  1024
#define DIM     512
#define NCTA    128          // 8 b-groups x 16 j-groups; co-resident on 148 SMs
#define NBG     8            // b-groups
#define FANIN   16           // CTAs per b-group

#define HSTRIDE 576          // staged row stride: 16 chunks x (32 data + 4 pad)
#define PROW    33           // part row stride (floats)
#define PSEG    (8 * PROW)   // part segment stride (264 floats)

// ---------------- scratch (device globals; no allocations) ------------------
__device__ float    g_h[2][BATCH * DIM];     // ping-pong hidden state
__device__ unsigned g_bar[TSTEPS * NBG];     // per-(step, b-group) counters

// ---------------- f32x2 packed-FMA helpers (sm_100+ PTX) --------------------
static __device__ __forceinline__ unsigned long long packf2(float lo, float hi) {
    unsigned long long r;
    asm("mov.b64 %0, {%1, %2};" : "=l"(r) : "f"(lo), "f"(hi));
    return r;
}
static __device__ __forceinline__ void unpackf2(unsigned long long v, float& lo, float& hi) {
    asm("mov.b64 {%0, %1}, %2;" : "=f"(lo), "=f"(hi) : "l"(v));
}
static __device__ __forceinline__ unsigned long long fma2(
    unsigned long long a, unsigned long long b, unsigned long long c) {
    unsigned long long d;
    asm("fma.rn.f32x2 %0, %1, %2, %3;" : "=l"(d) : "l"(a), "l"(b), "l"(c));
    return d;
}

// Padded staged-tile address: logical (row, float4-chunk c4) -> float offset.
// Every 32-float chunk ch sits at 36*ch (+4 pad per chunk, NO overlap).
// A warp's two k-halves are 36 floats = 144B apart -> disjoint bank quads
// (banks b..b+3 vs b+4..b+7) -> LDS.128 conflict-free.
static __device__ __forceinline__ int sw_off(int row, int c4) {
    return row * HSTRIDE + c4 * 4 + (c4 >> 3) * 4;
}

// ---------------------------------------------------------------------------
// Matmul partials: thread = (warp w: k-slice 64) x (cg: col pair) x (ks: k half)
// Computes 8 rows x 2 cols over 32 k; writes part[seg][row][col].
//   smoff = w*72 + ks*36   (padded base for logical k = w*64 + ks*32)
// Per warp: 64 LDS.128 (conflict-free) + 256 fma2.
// ---------------------------------------------------------------------------
static __device__ __forceinline__ void mm_partials(
    const float* __restrict__ sm, const unsigned long long w2[2][16],
    int smoff, int seg, int cg, float* __restrict__ part)
{
    unsigned long long acc[8][2];
#pragma unroll
    for (int r = 0; r < 8; r++) { acc[r][0] = 0ULL; acc[r][1] = 0ULL; }

#pragma unroll
    for (int m = 0; m < 8; m++) {
#pragma unroll
        for (int r = 0; r < 8; r++) {
            ulonglong2 h2 = *(const ulonglong2*)(sm + r * HSTRIDE + smoff + m * 4);
            acc[r][0] = fma2(h2.x, w2[0][2 * m + 0], acc[r][0]);
            acc[r][0] = fma2(h2.y, w2[0][2 * m + 1], acc[r][0]);
            acc[r][1] = fma2(h2.x, w2[1][2 * m + 0], acc[r][1]);
            acc[r][1] = fma2(h2.y, w2[1][2 * m + 1], acc[r][1]);
        }
    }
#pragma unroll
    for (int r = 0; r < 8; r++) {
#pragma unroll
        for (int c = 0; c < 2; c++) {
            float lo, hi;
            unpackf2(acc[r][c], lo, hi);
            part[seg * PSEG + r * PROW + cg * 2 + c] = lo + hi;
        }
    }
}

// ---------------------------------------------------------------------------
// Fused persistent kernel: h_{t+1} = tanh( (x_t@W + b) + h_t@Wr )
// CTA c: rows [b0,b0+8), cols [j0,j0+32). xw for t+1 computed in the
// barrier arrive->wait window. Per-b-group release/acquire barrier (fan-in 16).
// ---------------------------------------------------------------------------
__global__ void __launch_bounds__(256, 1) rnn_fused_kernel(
    const float* __restrict__ W,      // [512,512] row-major
    const float* __restrict__ Wr,     // [512,512] row-major
    const float* __restrict__ x,      // [64,1024,512]
    const float* __restrict__ bias,   // [512]
    float* __restrict__ out)          // [64,512]
{
    __shared__ float hs[8 * HSTRIDE];        // staged h tile (padded)  18 KB
    __shared__ float xs[8 * HSTRIDE];        // staged x tile (padded)  18 KB
    __shared__ float part[16 * PSEG];        // partials [16][8][33]    16.5 KB

    const int tid  = threadIdx.x;
    const int w    = tid >> 5;               // warp: k-slice [w*64, +64)
    const int lane = tid & 31;
    const int cg   = lane >> 1;              // col pair: cols j0 + cg*2 + {0,1}
    const int ks   = lane & 1;               // k half within slice
    const int c    = blockIdx.x;
    const int b0   = (c >> 4) * 8;
    const int j0   = (c & 15) * 32;
    const int bg   = c >> 4;

    const int kb    = w * 64 + ks * 32;      // logical k base
    const int smoff = w * 72 + ks * 36;      // padded smem base (chunk 2w+ks)
    const int seg   = w * 2 + ks;

    // persistent packed weights: (k, k+1) pairs for this thread's 2 columns
    unsigned long long wr2[2][16], wx2[2][16];
#pragma unroll
    for (int cc = 0; cc < 2; cc++) {
        const int j = j0 + cg * 2 + cc;
#pragma unroll
        for (int p = 0; p < 16; p++) {
            const int k = kb + 2 * p;
            wr2[cc][p] = packf2(Wr[(size_t)k * DIM + j], Wr[(size_t)(k + 1) * DIM + j]);
            wx2[cc][p] = packf2(W[(size_t)k * DIM + j],  W[(size_t)(k + 1) * DIM + j]);
        }
    }
    const int   rrow = tid >> 5;             // reduce-phase output row
    const int   rcol = tid & 31;             // reduce-phase output col
    const float bv   = bias[j0 + rcol];

    // ---- prologue: xw for t=0 ----
#pragma unroll
    for (int q = 0; q < 4; q++) {
        int idx = tid + q * 256, row = idx >> 7, c4 = idx & 127;
        *(float4*)&xs[sw_off(row, c4)] =
            __ldg((const float4*)(x + ((size_t)(b0 + row) * TSTEPS + 0) * DIM) + c4);
    }
    __syncthreads();
    mm_partials(xs, wx2, smoff, seg, cg, part);
    __syncthreads();
    float xw_cur = bv;
#pragma unroll
    for (int s8 = 0; s8 < 16; s8++) xw_cur += part[s8 * PSEG + rrow * PROW + rcol];
    __syncthreads();

    for (int t = 0; t < TSTEPS; t++) {
        // ---- stage h tile (L2-coherent) + prefetch x[t+1] into regs ----
        const float4* hsrc = (const float4*)(g_h[t & 1] + b0 * DIM);
        float4 xt[4];
        const int tn = (t + 1 < TSTEPS) ? (t + 1) : (TSTEPS - 1);
#pragma unroll
        for (int q = 0; q < 4; q++) {
            int idx = tid + q * 256, row = idx >> 7, c4 = idx & 127;
            *(float4*)&hs[sw_off(row, c4)] = __ldcg(hsrc + idx);
            xt[q] = __ldg((const float4*)(
                x + ((size_t)(b0 + row) * TSTEPS + tn) * DIM) + c4);
        }
        __syncthreads();

        // ---- recurrence: h_t @ Wr ----
        mm_partials(hs, wr2, smoff, seg, cg, part);
        __syncthreads();

        // ---- reduce + tanh + store h ----
        float s = xw_cur;
#pragma unroll
        for (int s8 = 0; s8 < 16; s8++) s += part[s8 * PSEG + rrow * PROW + rcol];
        float hv = tanhf(s);
        if (t == TSTEPS - 1) {
            out[(b0 + rrow) * DIM + j0 + rcol] = hv;
            return;
        }
        __stcg(&g_h[(t + 1) & 1][(b0 + rrow) * DIM + j0 + rcol], hv);
        __syncthreads();                      // all CTA stores done, part reads done

        // ---- arrive (release; fan-in 16 within b-group) ----
        if (tid == 0) {
            unsigned* ctr = &g_bar[t * NBG + bg];
            asm volatile("red.release.gpu.global.add.u32 [%0], %1;"
                         :: "l"(ctr), "r"(1u) : "memory");
        }

        // ---- gemm for t+1 fills the wait window ----
#pragma unroll
        for (int q = 0; q < 4; q++) {
            int idx = tid + q * 256, row = idx >> 7, c4 = idx & 127;
            *(float4*)&xs[sw_off(row, c4)] = xt[q];
        }
        __syncthreads();
        mm_partials(xs, wx2, smoff, seg, cg, part);
        __syncthreads();
        float s2 = bv;
#pragma unroll
        for (int s8 = 0; s8 < 16; s8++) s2 += part[s8 * PSEG + rrow * PROW + rcol];
        xw_cur = s2;

        // ---- wait (acquire) ----
        if (tid == 0) {
            const unsigned* ctr = &g_bar[t * NBG + bg];
            unsigned v;
            do {
                asm volatile("ld.acquire.gpu.global.u32 %0, [%1];"
                             : "=r"(v) : "l"(ctr) : "memory");
            } while (v < FANIN);
        }
        __syncthreads();
    }
}

// ============================================================================
extern "C" void kernel_launch(void* const* d_in, const int* in_sizes, int n_in,
                              void* d_out, int out_size)
{
    const float* x    = (const float*)d_in[0];   // [64,1024,512]
    const float* W    = (const float*)d_in[1];   // [512,512]
    const float* Wr   = (const float*)d_in[2];   // [512,512]
    const float* bias = (const float*)d_in[3];   // [512]
    float* out = (float*)d_out;                  // [64,512]

    void* bar_p; cudaGetSymbolAddress(&bar_p, g_bar);
    void* h_p;   cudaGetSymbolAddress(&h_p, g_h);

    // per-launch resets (graph-capturable, replay-safe)
    cudaMemsetAsync(bar_p, 0, sizeof(unsigned) * TSTEPS * NBG);
    cudaMemsetAsync(h_p, 0, sizeof(float) * BATCH * DIM);   // h_0 = 0 (buffer 0)

    rnn_fused_kernel<<<NCTA, 256>>>(W, Wr, x, bias, out);
}